// round 13
// baseline (speedup 1.0000x reference)
#include <cuda_runtime.h>

#define NF    32
#define NDOF  29
#define BLK   128           // 64 batches per block, 2 threads per batch (rows 01 / 23)
#define SLOT  17            // float4 stride per slot row in slab (odd => conflict-free)

struct FKConst {
    float4 cst[NF * 9];     // per (frame, row j 0..2): cA, cB, cC
    int    slot[NF];
    int    mslot[NF];
    float  mm[NF];
    float  mo[NF];
};

__constant__ FKConst c_fk;
__device__   FKConst g_fk;

// ---------------------------------------------------------------------------
// Prep kernel: derive per-(frame,row) constants + ctrl/mimic meta (uniform).
//   cA = (O_j.xyz, O_j.w)
//   cB = (O_j x k [revolute], O_j.k [prismatic])
//   cC = ((O_j.k)k - O_j.xyz [revolute], 0)
// L_j.xyz = cA + sn*cB + (1-cs)*cC ;  L_j.w = a*cB.w + cA.w
// ---------------------------------------------------------------------------
__global__ void fk_prep(const float* __restrict__ axes,
                        const float* __restrict__ origins,
                        const float* __restrict__ mmult,
                        const float* __restrict__ moff,
                        const int*   __restrict__ ctrl,
                        const int*   __restrict__ msrc,
                        const int*   __restrict__ mdst,
                        const int*   __restrict__ types)
{
    const int tid = threadIdx.x;     // 128 threads
    if (tid < NF * 3) {
        const int f  = tid / 3;
        const int rr = tid - f * 3;
        const float4 orow = *reinterpret_cast<const float4*>(origins + f * 16 + rr * 4);
        const float kx = axes[f * 3 + 0], ky = axes[f * 3 + 1], kz = axes[f * 3 + 2];
        const int   ty = types[f];
        const float vr = orow.x * kx + orow.y * ky + orow.z * kz;
        float bx = 0.f, by = 0.f, bz = 0.f, cx = 0.f, cy = 0.f, cz = 0.f, ve = 0.f;
        if (ty == 1) {
            bx = orow.y * kz - orow.z * ky;
            by = orow.z * kx - orow.x * kz;
            bz = orow.x * ky - orow.y * kx;
            cx = fmaf(vr, kx, -orow.x);
            cy = fmaf(vr, ky, -orow.y);
            cz = fmaf(vr, kz, -orow.z);
        } else if (ty == 2) {
            ve = vr;
        }
        g_fk.cst[(f * 3 + rr) * 3 + 0] = make_float4(orow.x, orow.y, orow.z, orow.w);
        g_fk.cst[(f * 3 + rr) * 3 + 1] = make_float4(bx, by, bz, ve);
        g_fk.cst[(f * 3 + rr) * 3 + 2] = make_float4(cx, cy, cz, 0.f);
    }
    if (tid < NF) {
        const int f = tid;
        int slot = -1;
        for (int j = 0; j < NDOF; ++j) if (ctrl[j] == f) slot = j;
        g_fk.slot[f] = slot;
        int ms = -1; float mm = 0.f, mo = 0.f;
        for (int m = 0; m < 2; ++m) {
            if (mdst[m] == f) {
                const int sf = msrc[m];
                for (int j = 0; j < NDOF; ++j) if (ctrl[j] == sf) ms = j;
                mm = mmult[m]; mo = moff[m];
            }
        }
        g_fk.mslot[f] = ms; g_fk.mm[f] = mm; g_fk.mo[f] = mo;
    }
}

__global__ void __launch_bounds__(BLK, 7)
fk_kernel(const float* __restrict__ ja,        // [B, 29]
          float*       __restrict__ out,       // [B, 32, 4, 4]
          int Bn)
{
    // slab: per warp, 8 slots (2 frames x 4 rows) x 17 float4 (16 batches + pad)
    __shared__ __align__(16) float4 s_slab[4 * 8 * SLOT];   // 8.7 KB
    __shared__ float s_angF[NF * 64];                       // 8 KB
    __shared__ float s_raw[64 * NDOF];                      // 7.4 KB

    const int tid  = threadIdx.x;
    const int lane = tid & 31;
    const int wid  = tid >> 5;
    const int h    = lane >> 4;        // 0: rows 0,1   1: rows 2,3
    const int btw  = lane & 15;        // batch within warp
    const int bloc = wid * 16 + btw;   // batch within block
    const int b0   = blockIdx.x * 64;

    // ---- stage raw joint angles (coalesced) ----
    for (int i = tid; i < 64 * NDOF; i += BLK) {
        const int bb = i / NDOF;
        s_raw[i] = (b0 + bb < Bn) ? ja[(size_t)b0 * NDOF + i] : 0.f;
    }
    __syncthreads();

    // ---- resolve final per-(frame,batch) angles (meta via constant bank) ----
    for (int i = tid; i < NF * 64; i += BLK) {
        const int f  = i >> 6;
        const int bb = i & 63;
        const int sl = c_fk.slot[f];
        float a;
        if (sl >= 0) a = s_raw[bb * NDOF + sl];
        else {
            const int ms = c_fk.mslot[f];
            a = (ms >= 0) ? fmaf(s_raw[bb * NDOF + ms], c_fk.mm[f], c_fk.mo[f]) : 0.f;
        }
        s_angF[i] = a;
    }
    __syncthreads();

    // ---- main chain: 2 threads per batch (rows 2h, 2h+1), LDCU constants ----
    float A[4]  = {0.f, 0.f, 0.f, 0.f};
    float Bv[4] = {0.f, 0.f, 0.f, 0.f};
    A[2 * h]      = 1.f;
    Bv[2 * h + 1] = 1.f;
    float QA[4], QB[4];
    #pragma unroll
    for (int j = 0; j < 4; ++j) { QA[j] = 0.f; QB[j] = 0.f; }

    float4* const wslab = s_slab + wid * (8 * SLOT);
    float4* const out4  = reinterpret_cast<float4*>(out);

    #pragma unroll
    for (int c = 0; c < NF / 2; ++c) {
        // -- phase A: build 2 independent local transforms from constant bank --
        float L[2][12];
        #pragma unroll
        for (int ff = 0; ff < 2; ++ff) {
            const int f = c * 2 + ff;
            const float a = s_angF[f * 64 + bloc];
            const float sn = __sinf(a);
            const float cs = __cosf(a);
            const float C = 1.f - cs;
            #pragma unroll
            for (int j = 0; j < 3; ++j) {
                const float4 cA = c_fk.cst[(f * 3 + j) * 3 + 0];
                const float4 cB = c_fk.cst[(f * 3 + j) * 3 + 1];
                const float4 cC = c_fk.cst[(f * 3 + j) * 3 + 2];
                L[ff][j * 4 + 0] = fmaf(C, cC.x, fmaf(sn, cB.x, cA.x));
                L[ff][j * 4 + 1] = fmaf(C, cC.y, fmaf(sn, cB.y, cA.y));
                L[ff][j * 4 + 2] = fmaf(C, cC.z, fmaf(sn, cB.z, cA.z));
                L[ff][j * 4 + 3] = fmaf(a, cB.w, cA.w);
            }
        }

        // -- phase B: serial row updates + stage --
        #pragma unroll
        for (int ff = 0; ff < 2; ++ff) {
            const int f = c * 2 + ff;
            if (f >= 30) {
                #pragma unroll
                for (int j = 0; j < 4; ++j) { A[j] = QA[j]; Bv[j] = QB[j]; }
            }
            {
                const float p0 = A[0], p1 = A[1], p2 = A[2], p3 = A[3];
                A[0] = fmaf(p0, L[ff][0], fmaf(p1, L[ff][4], p2 * L[ff][8]));
                A[1] = fmaf(p0, L[ff][1], fmaf(p1, L[ff][5], p2 * L[ff][9]));
                A[2] = fmaf(p0, L[ff][2], fmaf(p1, L[ff][6], p2 * L[ff][10]));
                A[3] = fmaf(p0, L[ff][3], fmaf(p1, L[ff][7], fmaf(p2, L[ff][11], p3)));
            }
            {
                const float p0 = Bv[0], p1 = Bv[1], p2 = Bv[2], p3 = Bv[3];
                Bv[0] = fmaf(p0, L[ff][0], fmaf(p1, L[ff][4], p2 * L[ff][8]));
                Bv[1] = fmaf(p0, L[ff][1], fmaf(p1, L[ff][5], p2 * L[ff][9]));
                Bv[2] = fmaf(p0, L[ff][2], fmaf(p1, L[ff][6], p2 * L[ff][10]));
                Bv[3] = fmaf(p0, L[ff][3], fmaf(p1, L[ff][7], fmaf(p2, L[ff][11], p3)));
            }
            if (f == 10) {
                #pragma unroll
                for (int j = 0; j < 4; ++j) { QA[j] = A[j]; QB[j] = Bv[j]; }
            }
            // stage: slot = ff*4 + row;  [slot][batch-within-warp]
            wslab[(ff * 4 + 2 * h + 0) * SLOT + btw] = make_float4(A[0], A[1], A[2], A[3]);
            wslab[(ff * 4 + 2 * h + 1) * SLOT + btw] = make_float4(Bv[0], Bv[1], Bv[2], Bv[3]);
        }

        __syncwarp();

        // -- flush: 16 batches x 8 float4; each iter = 4 batches x 128 B contiguous --
        #pragma unroll
        for (int it = 0; it < 4; ++it) {
            const int v = it * 32 + lane;
            const int b = v >> 3;               // batch within warp (0..15)
            const int w = v & 7;                // float4 within 2-frame chunk
            const float4 val = wslab[w * SLOT + b];
            const int gb = b0 + wid * 16 + b;
            if (gb < Bn)
                out4[(size_t)gb * (NF * 4) + c * 8 + w] = val;
        }

        __syncwarp();
    }
}

extern "C" void kernel_launch(void* const* d_in, const int* in_sizes, int n_in,
                              void* d_out, int out_size) {
    const float* ja      = (const float*)d_in[0];
    const float* axes    = (const float*)d_in[1];
    const float* origins = (const float*)d_in[2];
    const float* mm      = (const float*)d_in[3];
    const float* mo      = (const float*)d_in[4];
    const int*   ctrl    = (const int*)d_in[5];
    const int*   msrc    = (const int*)d_in[6];
    const int*   mdst    = (const int*)d_in[7];
    const int*   types   = (const int*)d_in[8];
    float*       out     = (float*)d_out;

    const int Bn = in_sizes[0] / NDOF;

    // 1) derive constants on device
    fk_prep<<<1, 128>>>(axes, origins, mm, mo, ctrl, msrc, mdst, types);

    // 2) copy into constant bank (D2D async — graph-capturable)
    void* g_ptr = nullptr;
    cudaGetSymbolAddress(&g_ptr, g_fk);
    cudaMemcpyToSymbolAsync(c_fk, g_ptr, sizeof(FKConst), 0, cudaMemcpyDeviceToDevice);

    // 3) main kernel: 64 batches per block, 2 threads per batch
    const int grid = (Bn + 63) / 64;
    fk_kernel<<<grid, BLK>>>(ja, out, Bn);
}

// round 14
// speedup vs baseline: 1.3611x; 1.3611x over previous
#include <cuda_runtime.h>

#define NF    32
#define NDOF  29
#define BLK   64            // 64 batches per block, 1 thread per batch, 2 warps
#define TS    28            // slab floats per batch: 2 frames * 12 + 4 pad

__global__ void __launch_bounds__(BLK, 7)
fk_kernel(const float* __restrict__ ja,        // [B, 29]
          const float* __restrict__ axes,      // [32, 3]
          const float* __restrict__ origins,   // [32, 4, 4]
          const float* __restrict__ mmult,     // [2]
          const float* __restrict__ moff,      // [2]
          const int*   __restrict__ ctrl,      // [29]
          const int*   __restrict__ msrc,      // [2]
          const int*   __restrict__ mdst,      // [2]
          const int*   __restrict__ types,     // [32]
          float*       __restrict__ out,       // [B, 32, 4, 4]
          int Bn)
{
    // Per (frame, row j 0..2) constants, 3 x float4:
    //   cA = (O_j.xyz, O_j.w)
    //   cB = (O_j x k [revolute], O_j.k [prismatic])
    //   cC = ((O_j.k)k - O_j.xyz [revolute], 0)
    // L_j.xyz = cA + sn*cB + (1-cs)*cC ;  L_j.w = a*cB.w + cA.w
    __shared__ __align__(16) float4 s_cst[NF * 9];     // 4.5 KB
    __shared__ float4 s_meta[NF];                      // (src bits, mul, off, 0)
    __shared__ float  s_raw[BLK * NDOF];               // 7.4 KB
    __shared__ __align__(16) float s_slab[BLK * TS];   // 7 KB (warp-private halves)

    const int tid  = threadIdx.x;
    const int lane = tid & 31;
    const int wid  = tid >> 5;
    const int b0   = blockIdx.x * BLK;

    // ---- per-frame meta: unified (src, mul, off) so angle = fmaf(raw[src],mul,off) ----
    if (tid < NF) {
        const int f = tid;
        int slot = -1;
        for (int j = 0; j < NDOF; ++j) if (ctrl[j] == f) slot = j;
        int src = 0; float mul = 0.f, off = 0.f;
        if (slot >= 0) { src = slot; mul = 1.f; off = 0.f; }
        else {
            for (int m = 0; m < 2; ++m) {
                if (mdst[m] == f) {
                    const int sf = msrc[m];
                    for (int j = 0; j < NDOF; ++j) if (ctrl[j] == sf) src = j;
                    mul = mmult[m]; off = moff[m];
                }
            }
        }
        s_meta[f] = make_float4(__int_as_float(src), mul, off, 0.f);
    }

    // ---- per (frame,row) constants ----
    for (int i = tid; i < NF * 3; i += BLK) {
        const int f  = i / 3;
        const int rr = i - f * 3;
        const float4 orow = *reinterpret_cast<const float4*>(origins + f * 16 + rr * 4);
        const float kx = axes[f * 3 + 0], ky = axes[f * 3 + 1], kz = axes[f * 3 + 2];
        const int   ty = types[f];
        const float vr = orow.x * kx + orow.y * ky + orow.z * kz;
        float bx = 0.f, by = 0.f, bz = 0.f, cx = 0.f, cy = 0.f, cz = 0.f, ve = 0.f;
        if (ty == 1) {
            bx = orow.y * kz - orow.z * ky;
            by = orow.z * kx - orow.x * kz;
            bz = orow.x * ky - orow.y * kx;
            cx = fmaf(vr, kx, -orow.x);
            cy = fmaf(vr, ky, -orow.y);
            cz = fmaf(vr, kz, -orow.z);
        } else if (ty == 2) {
            ve = vr;
        }
        s_cst[(f * 3 + rr) * 3 + 0] = make_float4(orow.x, orow.y, orow.z, orow.w);
        s_cst[(f * 3 + rr) * 3 + 1] = make_float4(bx, by, bz, ve);
        s_cst[(f * 3 + rr) * 3 + 2] = make_float4(cx, cy, cz, 0.f);
    }

    // ---- stage raw joint angles (coalesced) ----
    for (int i = tid; i < BLK * NDOF; i += BLK) {
        const int bb = i / NDOF;
        s_raw[i] = (b0 + bb < Bn) ? ja[(size_t)b0 * NDOF + i] : 0.f;
    }
    __syncthreads();

    // ---- L build from constants + on-the-fly angle (lane stride 29: conflict-free) ----
    auto buildL = [&](int c, float L[2][12]) {
        #pragma unroll
        for (int ff = 0; ff < 2; ++ff) {
            const int f = c * 2 + ff;
            const float4 mt = s_meta[f];
            const float  a  = fmaf(s_raw[tid * NDOF + __float_as_int(mt.x)], mt.y, mt.z);
            const float sn = __sinf(a);
            const float cs = __cosf(a);
            const float C  = 1.f - cs;
            const float4* cf = s_cst + f * 9;
            #pragma unroll
            for (int j = 0; j < 3; ++j) {
                const float4 cA = cf[j * 3 + 0];
                const float4 cB = cf[j * 3 + 1];
                const float4 cC = cf[j * 3 + 2];
                L[ff][j * 4 + 0] = fmaf(C, cC.x, fmaf(sn, cB.x, cA.x));
                L[ff][j * 4 + 1] = fmaf(C, cC.y, fmaf(sn, cB.y, cA.y));
                L[ff][j * 4 + 2] = fmaf(C, cC.z, fmaf(sn, cB.z, cA.z));
                L[ff][j * 4 + 3] = fmaf(a, cB.w, cA.w);
            }
        }
    };

    // ---- main chain: software-pipelined chunks, warp-autonomous flush ----
    float P[12];
    #pragma unroll
    for (int j = 0; j < 12; ++j) P[j] = 0.f;
    P[0] = 1.f; P[5] = 1.f; P[10] = 1.f;
    float Q[12];
    #pragma unroll
    for (int j = 0; j < 12; ++j) Q[j] = 0.f;

    float* const wslab = s_slab + wid * (32 * TS);
    float4* const out4 = reinterpret_cast<float4*>(out);

    float L[2][12];
    buildL(0, L);

    #pragma unroll
    for (int c = 0; c < NF / 2; ++c) {
        // -- phase B: serial chain updates + stage (uses pre-built L) --
        #pragma unroll
        for (int ff = 0; ff < 2; ++ff) {
            const int f = c * 2 + ff;
            if (f >= 30) {
                #pragma unroll
                for (int j = 0; j < 12; ++j) P[j] = Q[j];
            }
            #pragma unroll
            for (int rr = 0; rr < 3; ++rr) {
                const float p0 = P[rr * 4 + 0], p1 = P[rr * 4 + 1];
                const float p2 = P[rr * 4 + 2], p3 = P[rr * 4 + 3];
                P[rr * 4 + 0] = fmaf(p0, L[ff][0], fmaf(p1, L[ff][4], p2 * L[ff][8]));
                P[rr * 4 + 1] = fmaf(p0, L[ff][1], fmaf(p1, L[ff][5], p2 * L[ff][9]));
                P[rr * 4 + 2] = fmaf(p0, L[ff][2], fmaf(p1, L[ff][6], p2 * L[ff][10]));
                P[rr * 4 + 3] = fmaf(p0, L[ff][3], fmaf(p1, L[ff][7], fmaf(p2, L[ff][11], p3)));
            }
            if (f == 10) {
                #pragma unroll
                for (int j = 0; j < 12; ++j) Q[j] = P[j];
            }
            float4* sp = reinterpret_cast<float4*>(wslab + lane * TS + ff * 12);
            sp[0] = make_float4(P[0], P[1], P[2],  P[3]);
            sp[1] = make_float4(P[4], P[5], P[6],  P[7]);
            sp[2] = make_float4(P[8], P[9], P[10], P[11]);
        }

        __syncwarp();

        // -- pipelined: build next chunk's L while this chunk's flush drains --
        float Ln[2][12];
        if (c < NF / 2 - 1) buildL(c + 1, Ln);

        // -- flush: each iter = 4 batches x 128 B contiguous, streaming stores --
        #pragma unroll
        for (int it = 0; it < 8; ++it) {
            const int v = it * 32 + lane;
            const int b = v >> 3;               // warp-local batch (0..31)
            const int w = v & 7;                // frame*4 + row within chunk
            const int fi = w >> 2;
            const int rr = w & 3;
            float4 val;
            if (rr < 3) val = *reinterpret_cast<const float4*>(wslab + b * TS + fi * 12 + rr * 4);
            else        val = make_float4(0.f, 0.f, 0.f, 1.f);
            const int gbat = b0 + (wid << 5) + b;
            if (gbat < Bn)
                __stcs(&out4[(size_t)gbat * (NF * 4) + c * 8 + w], val);
        }

        __syncwarp();

        if (c < NF / 2 - 1) {
            #pragma unroll
            for (int ff = 0; ff < 2; ++ff)
                #pragma unroll
                for (int j = 0; j < 12; ++j) L[ff][j] = Ln[ff][j];
        }
    }
}

extern "C" void kernel_launch(void* const* d_in, const int* in_sizes, int n_in,
                              void* d_out, int out_size) {
    const float* ja      = (const float*)d_in[0];
    const float* axes    = (const float*)d_in[1];
    const float* origins = (const float*)d_in[2];
    const float* mm      = (const float*)d_in[3];
    const float* mo      = (const float*)d_in[4];
    const int*   ctrl    = (const int*)d_in[5];
    const int*   msrc    = (const int*)d_in[6];
    const int*   mdst    = (const int*)d_in[7];
    const int*   types   = (const int*)d_in[8];
    float*       out     = (float*)d_out;

    const int Bn   = in_sizes[0] / NDOF;
    const int grid = (Bn + BLK - 1) / BLK;
    fk_kernel<<<grid, BLK>>>(ja, axes, origins, mm, mo, ctrl, msrc, mdst, types, out, Bn);
}